// round 1
// baseline (speedup 1.0000x reference)
#include <cuda_runtime.h>
#include <math_constants.h>

// Problem constants
#define Nn 64
#define Cc 3
#define Ll 4096
#define Kk 128
#define Ss 64
#define Ww (Ll - Ss + 1)   // 4033 windows

// Tiling
#define CHUNK 64           // windows per CTA inner chunk
#define WT 16              // windows per thread
#define TILES 8            // window tiles per (n,c) row
#define WIN_PER_CTA 512    // TILES*WIN_PER_CTA >= Ww
#define THREADS 256

// Scratch (static device globals: allocation-free)
__device__ float x2g[Nn * Cc * Ww];   // sliding ||x_w||^2
__device__ float s2g[Cc * Kk];        // ||s||^2

// ---------------------------------------------------------------------------
// f32x2 packed FMA helpers
// ---------------------------------------------------------------------------
union F2 {
    float2 f;
    unsigned long long u;
};

__device__ __forceinline__ void fma2(F2& d, const F2& a, const F2& b) {
    asm("fma.rn.f32x2 %0, %1, %2, %0;" : "+l"(d.u) : "l"(a.u), "l"(b.u));
}

// ---------------------------------------------------------------------------
// Kernel 1: init output to +inf bits, compute shapelet norms s2
// ---------------------------------------------------------------------------
__global__ void prep_kernel(const float* __restrict__ sh, int* __restrict__ outb) {
    int t = blockIdx.x * blockDim.x + threadIdx.x;
    if (t < Nn * Kk) outb[t] = 0x7F800000;  // +inf
    if (t < Cc * Kk) {
        const float* p = sh + t * Ss;
        float s = 0.f;
#pragma unroll
        for (int i = 0; i < Ss; i++) s = fmaf(p[i], p[i], s);
        s2g[t] = s;
    }
}

// ---------------------------------------------------------------------------
// Kernel 2: sliding window squared norms x2g[n,c,w] = sum_s x[n,c,w+s]^2
// ---------------------------------------------------------------------------
__global__ void x2_kernel(const float* __restrict__ x) {
    __shared__ float xs[Ll];
    int nc = blockIdx.x;
    const float* xr = x + nc * Ll;
    for (int i = threadIdx.x; i < Ll; i += THREADS) xs[i] = xr[i];
    __syncthreads();
    for (int w = threadIdx.x; w < Ww; w += THREADS) {
        float s = 0.f;
#pragma unroll
        for (int i = 0; i < Ss; i++) {
            float v = xs[w + i];
            s = fmaf(v, v, s);
        }
        x2g[nc * Ww + w] = s;
    }
}

// ---------------------------------------------------------------------------
// Kernel 3: main sliding-dot + min kernel
//   CTA: one (n, c, window-tile of 512). 8 warps = 2 k-halves x 4 window-groups.
//   Thread: k-pair (k0, k0+1), WT=16 consecutive windows, f32x2 accumulators.
// ---------------------------------------------------------------------------
__global__ void __launch_bounds__(THREADS, 2)
main_kernel(const float* __restrict__ x, const float* __restrict__ sh,
            int* __restrict__ outb) {
    __shared__ float shT[Ss][Kk + 2];           // transposed shapelets, stride 130
    __shared__ float2 xd[CHUNK + Ss + 16];      // duplicated {x,x} strip
    __shared__ float x2s[CHUNK];

    int b = blockIdx.x;
    int tile = b % TILES;
    int nc = b / TILES;
    int c = nc % Cc;
    int n = nc / Cc;

    int tid = threadIdx.x;

    // Load shapelets transposed: shT[s][k] = sh[c][k][s]
    const float* shc = sh + c * (Kk * Ss);
    for (int i = tid; i < Kk * Ss; i += THREADS) {
        int k = i / Ss, s = i % Ss;
        shT[s][k] = shc[i];
    }

    int lane = tid & 31;
    int warp = tid >> 5;
    int kh = warp & 1;     // k half (0: k<64, 1: k>=64)
    int wg = warp >> 1;    // window group 0..3
    int k0 = kh * 64 + lane * 2;
    int o = wg * WT;       // window offset within chunk

    float s2a = s2g[c * Kk + k0];
    float s2b = s2g[c * Kk + k0 + 1];
    float m0 = CUDART_INF_F, m1 = CUDART_INF_F;

    const float* xr = x + nc * Ll;
    const float* x2r = x2g + nc * Ww;
    int wctabase = tile * WIN_PER_CTA;

    // pointer to this thread's k-pair column in shT (float2 row stride = 65)
    const float2* shp = (const float2*)(&shT[0][k0]);

    for (int ch = 0; ch < WIN_PER_CTA / CHUNK; ch++) {
        int wbase = wctabase + ch * CHUNK;

        __syncthreads();  // previous chunk readers done before overwrite
        for (int i = tid; i < CHUNK + Ss; i += THREADS) {
            int g = wbase + i;
            float v = (g < Ll) ? xr[g] : 0.f;
            xd[i] = make_float2(v, v);
        }
        for (int i = tid; i < CHUNK; i += THREADS)
            x2s[i] = (wbase + i < Ww) ? x2r[wbase + i] : CUDART_INF_F;
        __syncthreads();

        // ring of 16 duplicated x pairs: ring[r] = xd[o + s0 + r]
        F2 ring[16];
#pragma unroll
        for (int r = 0; r < 16; r++) ring[r].f = xd[o + r];

        F2 acc[16];
#pragma unroll
        for (int j = 0; j < 16; j++) acc[j].u = 0ULL;

#pragma unroll 1
        for (int s0 = 0; s0 < Ss; s0 += 16) {
#pragma unroll
            for (int ds = 0; ds < 16; ds++) {
                F2 shv;
                shv.f = shp[(s0 + ds) * ((Kk + 2) / 2)];
#pragma unroll
                for (int j = 0; j < 16; j++) {
                    fma2(acc[j], ring[(ds + j) & 15], shv);
                }
                // refill slot ds for next outer iteration
                ring[ds].f = xd[o + s0 + 16 + ds];
            }
        }

        // epilogue: d2 = x2 + s2 - 2*dot ; running min
#pragma unroll
        for (int j = 0; j < 16; j++) {
            float xv = x2s[o + j];   // +inf for padded windows
            float d0 = fmaf(-2.f, acc[j].f.x, xv + s2a);
            float d1 = fmaf(-2.f, acc[j].f.y, xv + s2b);
            m0 = fminf(m0, d0);
            m1 = fminf(m1, d1);
        }
    }

    // int-bit atomicMin == float min for non-NaN values
    atomicMin(&outb[n * Kk + k0],     __float_as_int(m0));
    atomicMin(&outb[n * Kk + k0 + 1], __float_as_int(m1));
}

// ---------------------------------------------------------------------------
// Kernel 4: convert min d2 bits -> sqrt(max(d2,0))
// ---------------------------------------------------------------------------
__global__ void finish_kernel(float* __restrict__ out) {
    int t = blockIdx.x * blockDim.x + threadIdx.x;
    if (t < Nn * Kk) {
        int bits = ((const int*)out)[t];
        float d2 = __int_as_float(bits);
        out[t] = sqrtf(fmaxf(d2, 0.f));
    }
}

// ---------------------------------------------------------------------------
extern "C" void kernel_launch(void* const* d_in, const int* in_sizes, int n_in,
                              void* d_out, int out_size) {
    const float* x  = (const float*)d_in[0];
    const float* sh = (const float*)d_in[1];
    // defensive: identify by element count (x = 786432, shapelets = 24576)
    if (n_in >= 2 && in_sizes[0] == Cc * Kk * Ss && in_sizes[1] == Nn * Cc * Ll) {
        x  = (const float*)d_in[1];
        sh = (const float*)d_in[0];
    }
    int* outb = (int*)d_out;

    prep_kernel<<<(Nn * Kk + THREADS - 1) / THREADS, THREADS>>>(sh, outb);
    x2_kernel<<<Nn * Cc, THREADS>>>(x);
    main_kernel<<<Nn * Cc * TILES, THREADS>>>(x, sh, outb);
    finish_kernel<<<(Nn * Kk + THREADS - 1) / THREADS, THREADS>>>((float*)d_out);
}

// round 3
// speedup vs baseline: 5.9309x; 5.9309x over previous
#include <cuda_runtime.h>
#include <cuda_fp16.h>
#include <math_constants.h>
#include <cstdint>

// ---------------------------------------------------------------- constants
#define NN 64
#define CC 3
#define NCC (NN*CC)        // 192 rows
#define LL 4096
#define KK 128             // shapelets
#define SS 64              // shapelet length
#define WW (LL - SS + 1)   // 4033 valid windows
#define PK 2112            // fp16-pair entries per row (covers 4224 padded elems)
#define GROUPS 8           // window groups of 512 per nc row
#define GRID (NCC*GROUPS)  // 1536 CTAs
#define TMAIN 256
#define TPREP 256

// ---------------------------------------------------------------- scratch
__device__ uint32_t g_xe[NCC*PK];    // even-parity packed fp16 pairs {x[2i],x[2i+1]}
__device__ uint32_t g_xo[NCC*PK];    // odd-parity  packed fp16 pairs {x[2i+1],x[2i+2]}
__device__ uint32_t g_shp[CC*KK*32]; // shapelet fp16 pairs, row-major (32 u32 per k-row)
__device__ float    g_x2[NCC*LL];    // sliding ||x_w||^2, +inf for w >= WW
__device__ float    g_s2[CC*KK];     // ||s||^2
__device__ int      g_minb[NN*KK];   // running min d^2 (int bits)

__device__ __forceinline__ uint32_t packh(float a, float b) {
    __half2 h = __floats2half2_rn(a, b);   // low = a, high = b
    return *(uint32_t*)&h;
}

// ---------------------------------------------------------------- prep
__global__ __launch_bounds__(TPREP) void prep_kernel(const float* __restrict__ x,
                                                     const float* __restrict__ sh) {
    __shared__ float xs[LL + 144];
    int r = blockIdx.x, tid = threadIdx.x;
    const float* xr = x + r * LL;
    for (int i = tid; i < LL; i += TPREP) xs[i] = xr[i];
    for (int i = LL + tid; i < LL + 144; i += TPREP) xs[i] = 0.f;
    __syncthreads();

    for (int i = tid; i < PK; i += TPREP) {
        float e0 = xs[2 * i], e1 = xs[2 * i + 1], e2 = xs[2 * i + 2];
        g_xe[r * PK + i] = packh(e0, e1);
        g_xo[r * PK + i] = packh(e1, e2);
    }
    for (int w = tid; w < LL; w += TPREP) {
        float s;
        if (w < WW) {
            s = 0.f;
#pragma unroll
            for (int i = 0; i < SS; i++) { float v = xs[w + i]; s = fmaf(v, v, s); }
        } else s = CUDART_INF_F;
        g_x2[r * LL + w] = s;
    }
    if (r == 0) {
        for (int i = tid; i < CC * KK * 32; i += TPREP) {
            int base = (i >> 5) * SS + (i & 31) * 2;
            g_shp[i] = packh(sh[base], sh[base + 1]);
        }
        for (int i = tid; i < CC * KK; i += TPREP) {
            const float* p = sh + i * SS;
            float s = 0.f;
#pragma unroll
            for (int j = 0; j < SS; j++) s = fmaf(p[j], p[j], s);
            g_s2[i] = s;
        }
    }
    if (r == 1) {
        for (int i = tid; i < NN * KK; i += TPREP) g_minb[i] = 0x7F800000;  // +inf
    }
}

// ---------------------------------------------------------------- mma wrapper
__device__ __forceinline__ void mma16816(float& c0, float& c1, float& c2, float& c3,
                                         uint32_t a0, uint32_t a1, uint32_t a2, uint32_t a3,
                                         uint32_t b0, uint32_t b1) {
    asm("mma.sync.aligned.m16n8k16.row.col.f32.f16.f16.f32 "
        "{%0,%1,%2,%3}, {%4,%5,%6,%7}, {%8,%9}, {%0,%1,%2,%3};"
        : "+f"(c0), "+f"(c1), "+f"(c2), "+f"(c3)
        : "r"(a0), "r"(a1), "r"(a2), "r"(a3), "r"(b0), "r"(b1));
}

// ---------------------------------------------------------------- main
// CTA = (nc row, group of 512 windows = 8 tiles of 64).
// 8 warps: wm = warp%4 -> 32 k-rows; wn = warp/4 -> 32 windows within tile of 64.
// Warp tile: m32 x n32 x k64. B fragments come straight from the parity strip
// (Hankel structure): b0 = {strip[n+k], strip[n+k+1]} = one u32 LDS.
__global__ __launch_bounds__(TMAIN) void main_kernel() {
    __shared__ uint32_t SE[296], SO[296];
    __shared__ float x2s[512];

    int b = blockIdx.x;
    int nc = b >> 3, grp = b & 7;
    int c = nc % CC, n = nc / CC;
    int tid = threadIdx.x, lane = tid & 31, warp = tid >> 5;
    int wm = warp & 3, wn = warp >> 2;
    int q = lane & 3, g = lane >> 2;

    int pbase = nc * PK + grp * 256;
    for (int i = tid; i < 296; i += TMAIN) { SE[i] = g_xe[pbase + i]; SO[i] = g_xo[pbase + i]; }
    for (int i = tid; i < 512; i += TMAIN) x2s[i] = g_x2[nc * LL + grp * 512 + i];

    // A fragments: register-resident shapelets, rows wm*32 .. wm*32+31
    uint32_t A[2][4][4];
    float s2v[2][2];
#pragma unroll
    for (int mt = 0; mt < 2; mt++) {
        int r0 = wm * 32 + mt * 16 + g;
        int r1 = r0 + 8;
        const uint32_t* ap0 = g_shp + (c * KK + r0) * 32;
        const uint32_t* ap1 = g_shp + (c * KK + r1) * 32;
#pragma unroll
        for (int ks = 0; ks < 4; ks++) {
            A[mt][ks][0] = ap0[ks * 8 + q];
            A[mt][ks][1] = ap1[ks * 8 + q];
            A[mt][ks][2] = ap0[ks * 8 + q + 4];
            A[mt][ks][3] = ap1[ks * 8 + q + 4];
        }
        s2v[mt][0] = g_s2[c * KK + r0];
        s2v[mt][1] = g_s2[c * KK + r1];
    }
    __syncthreads();

    // per-lane strip pointer: element index j = (win) + k, win = t*64+wn*32+nt*8+g,
    // k = ks*16 + q*2 (+8 for b1). parity(j) = g&1; word = j>>1.
    const uint32_t* sp = ((g & 1) ? SO : SE) + (g >> 1) + q + wn * 16;

    float mn[2][2] = {{CUDART_INF_F, CUDART_INF_F}, {CUDART_INF_F, CUDART_INF_F}};

#pragma unroll 1
    for (int t = 0; t < 8; t++) {
        float acc[2][4][4];
#pragma unroll
        for (int mt = 0; mt < 2; mt++)
#pragma unroll
            for (int nt = 0; nt < 4; nt++)
#pragma unroll
                for (int j = 0; j < 4; j++) acc[mt][nt][j] = 0.f;

#pragma unroll
        for (int ks = 0; ks < 4; ks++) {
#pragma unroll
            for (int nt = 0; nt < 4; nt++) {
                uint32_t b0 = sp[t * 32 + nt * 4 + ks * 8];
                uint32_t b1 = sp[t * 32 + nt * 4 + ks * 8 + 4];
                mma16816(acc[0][nt][0], acc[0][nt][1], acc[0][nt][2], acc[0][nt][3],
                         A[0][ks][0], A[0][ks][1], A[0][ks][2], A[0][ks][3], b0, b1);
                mma16816(acc[1][nt][0], acc[1][nt][1], acc[1][nt][2], acc[1][nt][3],
                         A[1][ks][0], A[1][ks][1], A[1][ks][2], A[1][ks][3], b0, b1);
            }
        }

        // epilogue: track min(x2[w] - 2*dot); +s2 folded in at the end
#pragma unroll
        for (int nt = 0; nt < 4; nt++) {
            int col = t * 64 + wn * 32 + nt * 8 + q * 2;
            float2 xv = *(const float2*)&x2s[col];
#pragma unroll
            for (int mt = 0; mt < 2; mt++) {
                mn[mt][0] = fminf(mn[mt][0], fmaf(-2.f, acc[mt][nt][0], xv.x));
                mn[mt][0] = fminf(mn[mt][0], fmaf(-2.f, acc[mt][nt][1], xv.y));
                mn[mt][1] = fminf(mn[mt][1], fmaf(-2.f, acc[mt][nt][2], xv.x));
                mn[mt][1] = fminf(mn[mt][1], fmaf(-2.f, acc[mt][nt][3], xv.y));
            }
        }
    }

    // reduce over the 4 lanes sharing the same rows (same g, q = 0..3)
#pragma unroll
    for (int mt = 0; mt < 2; mt++)
#pragma unroll
        for (int h = 0; h < 2; h++) {
            float v = mn[mt][h];
            v = fminf(v, __shfl_xor_sync(0xFFFFFFFFu, v, 1));
            v = fminf(v, __shfl_xor_sync(0xFFFFFFFFu, v, 2));
            if (q == 0) {
                int row = wm * 32 + mt * 16 + h * 8 + g;
                atomicMin(&g_minb[n * KK + row], __float_as_int(v + s2v[mt][h]));
            }
        }
}

// ---------------------------------------------------------------- finish
__global__ void finish_kernel(float* __restrict__ out) {
    int t = blockIdx.x * blockDim.x + threadIdx.x;
    if (t < NN * KK) {
        float d2 = __int_as_float(g_minb[t]);
        out[t] = sqrtf(fmaxf(d2, 0.f));
    }
}

// ---------------------------------------------------------------- launch
extern "C" void kernel_launch(void* const* d_in, const int* in_sizes, int n_in,
                              void* d_out, int out_size) {
    const float* x  = (const float*)d_in[0];
    const float* sh = (const float*)d_in[1];
    if (n_in >= 2 && in_sizes[0] == CC * KK * SS && in_sizes[1] == NN * CC * LL) {
        x  = (const float*)d_in[1];
        sh = (const float*)d_in[0];
    }
    prep_kernel<<<NCC, TPREP>>>(x, sh);
    main_kernel<<<GRID, TMAIN>>>();
    finish_kernel<<<(NN * KK + 255) / 256, 256>>>((float*)d_out);
}

// round 4
// speedup vs baseline: 6.1151x; 1.0311x over previous
#include <cuda_runtime.h>
#include <cuda_fp16.h>
#include <math_constants.h>
#include <cstdint>

// ---------------------------------------------------------------- constants
#define NN 64
#define CC 3
#define NCC (NN*CC)        // 192 rows
#define LL 4096
#define KK 128             // shapelets
#define SS 64              // shapelet length
#define WW (LL - SS + 1)   // 4033 valid windows
#define GROUPS 8           // window groups of 512 per nc row
#define GRID (NCC*GROUPS)  // 1536 CTAs
#define TMAIN 256

#define STRIP 600          // f32 strip elements per CTA (512 + 63 + pad, covers pack reads)

// ---------------------------------------------------------------- scratch
__device__ uint32_t g_shp[CC*KK*32]; // shapelet fp16 pairs, row-major (32 u32 per k-row)
__device__ float    g_s2[CC*KK];     // ||s||^2
__device__ int      g_minb[NN*KK];   // running min d^2 (int bits)
__device__ int      g_ctr;           // completion counter (zero-init, self-reset)

__device__ __forceinline__ uint32_t packh(float a, float b) {
    __half2 h = __floats2half2_rn(a, b);   // low = a, high = b
    return *(uint32_t*)&h;
}

// ---------------------------------------------------------------- prep (tiny)
__global__ __launch_bounds__(256) void prep_kernel(const float* __restrict__ sh) {
    int t = blockIdx.x * blockDim.x + threadIdx.x;
    int nt = gridDim.x * blockDim.x;
    for (int i = t; i < CC * KK * 32; i += nt) {
        int base = (i >> 5) * SS + (i & 31) * 2;
        g_shp[i] = packh(sh[base], sh[base + 1]);
    }
    for (int i = t; i < CC * KK; i += nt) {
        const float* p = sh + i * SS;
        float s = 0.f;
#pragma unroll
        for (int j = 0; j < SS; j++) s = fmaf(p[j], p[j], s);
        g_s2[i] = s;
    }
    for (int i = t; i < NN * KK; i += nt) g_minb[i] = 0x7F800000;  // +inf
}

// ---------------------------------------------------------------- mma wrapper
__device__ __forceinline__ void mma16816(float& c0, float& c1, float& c2, float& c3,
                                         uint32_t a0, uint32_t a1, uint32_t a2, uint32_t a3,
                                         uint32_t b0, uint32_t b1) {
    asm("mma.sync.aligned.m16n8k16.row.col.f32.f16.f16.f32 "
        "{%0,%1,%2,%3}, {%4,%5,%6,%7}, {%8,%9}, {%0,%1,%2,%3};"
        : "+f"(c0), "+f"(c1), "+f"(c2), "+f"(c3)
        : "r"(a0), "r"(a1), "r"(a2), "r"(a3), "r"(b0), "r"(b1));
}

// ---------------------------------------------------------------- main
// CTA = (nc row, group of 512 windows = 8 tiles of 64).
// Fused prologue: load f32 strip, pack fp16 parity strips, compute window norms.
// 8 warps: wm = warp%4 -> 32 k-rows; wn = warp/4 -> 32 windows within tile of 64.
// B fragments come straight from the parity strip (Hankel): 1 LDS.32 each.
__global__ __launch_bounds__(TMAIN) void main_kernel(const float* __restrict__ x,
                                                     float* __restrict__ out) {
    __shared__ float xs[STRIP];
    __shared__ uint32_t SE[296], SO[296];
    __shared__ float x2s[512];

    int b = blockIdx.x;
    int nc = b >> 3, grp = b & 7;
    int c = nc % CC, n = nc / CC;
    int tid = threadIdx.x, lane = tid & 31, warp = tid >> 5;
    int wm = warp & 3, wn = warp >> 2;
    int q = lane & 3, g = lane >> 2;

    int ebase = grp * 512;                       // strip start element in row
    const float* xr = x + nc * LL;

    // 1) f32 strip (zero-padded past end of row)
    for (int i = tid; i < STRIP; i += TMAIN) {
        int gidx = ebase + i;
        xs[i] = (gidx < LL) ? xr[gidx] : 0.f;
    }
    __syncthreads();

    // 2) fp16 parity packs + sliding window norms (exact, 2 windows/thread)
    for (int i = tid; i < 296; i += TMAIN) {
        float e0 = xs[2 * i], e1 = xs[2 * i + 1], e2 = xs[2 * i + 2];
        SE[i] = packh(e0, e1);
        SO[i] = packh(e1, e2);
    }
#pragma unroll
    for (int u = 0; u < 2; u++) {
        int w = u * TMAIN + tid;                 // 0..511 local window
        float s;
        if (ebase + w < WW) {
            s = 0.f;
#pragma unroll
            for (int i = 0; i < SS; i++) { float v = xs[w + i]; s = fmaf(v, v, s); }
        } else s = CUDART_INF_F;
        x2s[w] = s;
    }

    // 3) A fragments: register-resident shapelets, rows wm*32 .. wm*32+31
    uint32_t A[2][4][4];
    float s2v[2][2];
#pragma unroll
    for (int mt = 0; mt < 2; mt++) {
        int r0 = wm * 32 + mt * 16 + g;
        int r1 = r0 + 8;
        const uint32_t* ap0 = g_shp + (c * KK + r0) * 32;
        const uint32_t* ap1 = g_shp + (c * KK + r1) * 32;
#pragma unroll
        for (int ks = 0; ks < 4; ks++) {
            A[mt][ks][0] = ap0[ks * 8 + q];
            A[mt][ks][1] = ap1[ks * 8 + q];
            A[mt][ks][2] = ap0[ks * 8 + q + 4];
            A[mt][ks][3] = ap1[ks * 8 + q + 4];
        }
        s2v[mt][0] = g_s2[c * KK + r0];
        s2v[mt][1] = g_s2[c * KK + r1];
    }
    __syncthreads();

    // per-lane strip pointer (parity of element index = g&1)
    const uint32_t* sp = ((g & 1) ? SO : SE) + (g >> 1) + q + wn * 16;

    float mn[2][2] = {{CUDART_INF_F, CUDART_INF_F}, {CUDART_INF_F, CUDART_INF_F}};

#pragma unroll 1
    for (int t = 0; t < 8; t++) {
        float acc[2][4][4];
#pragma unroll
        for (int mt = 0; mt < 2; mt++)
#pragma unroll
            for (int nt = 0; nt < 4; nt++)
#pragma unroll
                for (int j = 0; j < 4; j++) acc[mt][nt][j] = 0.f;

#pragma unroll
        for (int ks = 0; ks < 4; ks++) {
#pragma unroll
            for (int nt = 0; nt < 4; nt++) {
                uint32_t b0 = sp[t * 32 + nt * 4 + ks * 8];
                uint32_t b1 = sp[t * 32 + nt * 4 + ks * 8 + 4];
                mma16816(acc[0][nt][0], acc[0][nt][1], acc[0][nt][2], acc[0][nt][3],
                         A[0][ks][0], A[0][ks][1], A[0][ks][2], A[0][ks][3], b0, b1);
                mma16816(acc[1][nt][0], acc[1][nt][1], acc[1][nt][2], acc[1][nt][3],
                         A[1][ks][0], A[1][ks][1], A[1][ks][2], A[1][ks][3], b0, b1);
            }
        }

        // epilogue: track min(x2[w] - 2*dot); +s2 folded in at the end
#pragma unroll
        for (int nt = 0; nt < 4; nt++) {
            int col = t * 64 + wn * 32 + nt * 8 + q * 2;
            float2 xv = *(const float2*)&x2s[col];
#pragma unroll
            for (int mt = 0; mt < 2; mt++) {
                mn[mt][0] = fminf(mn[mt][0], fmaf(-2.f, acc[mt][nt][0], xv.x));
                mn[mt][0] = fminf(mn[mt][0], fmaf(-2.f, acc[mt][nt][1], xv.y));
                mn[mt][1] = fminf(mn[mt][1], fmaf(-2.f, acc[mt][nt][2], xv.x));
                mn[mt][1] = fminf(mn[mt][1], fmaf(-2.f, acc[mt][nt][3], xv.y));
            }
        }
    }

    // reduce over the 4 lanes sharing the same rows (same g, q = 0..3)
#pragma unroll
    for (int mt = 0; mt < 2; mt++)
#pragma unroll
        for (int h = 0; h < 2; h++) {
            float v = mn[mt][h];
            v = fminf(v, __shfl_xor_sync(0xFFFFFFFFu, v, 1));
            v = fminf(v, __shfl_xor_sync(0xFFFFFFFFu, v, 2));
            if (q == 0) {
                int row = wm * 32 + mt * 16 + h * 8 + g;
                atomicMin(&g_minb[n * KK + row], __float_as_int(v + s2v[mt][h]));
            }
        }

    // last CTA finalizes: sqrt(min d^2) -> out
    __shared__ int lastFlag;
    __threadfence();
    __syncthreads();
    if (tid == 0) lastFlag = (atomicAdd(&g_ctr, 1) == GRID - 1);
    __syncthreads();
    if (lastFlag) {
        __threadfence();
        for (int i = tid; i < NN * KK; i += TMAIN) {
            float d2 = __int_as_float(g_minb[i]);
            out[i] = sqrtf(fmaxf(d2, 0.f));
        }
        __threadfence();
        if (tid == 0) g_ctr = 0;
    }
}

// ---------------------------------------------------------------- launch
extern "C" void kernel_launch(void* const* d_in, const int* in_sizes, int n_in,
                              void* d_out, int out_size) {
    const float* x  = (const float*)d_in[0];
    const float* sh = (const float*)d_in[1];
    if (n_in >= 2 && in_sizes[0] == CC * KK * SS && in_sizes[1] == NN * CC * LL) {
        x  = (const float*)d_in[1];
        sh = (const float*)d_in[0];
    }
    prep_kernel<<<8, 256>>>(sh);
    main_kernel<<<GRID, TMAIN>>>(x, (float*)d_out);
}

// round 5
// speedup vs baseline: 6.2962x; 1.0296x over previous
#include <cuda_runtime.h>
#include <cuda_fp16.h>
#include <math_constants.h>
#include <cstdint>

// ---------------------------------------------------------------- constants
#define NN 64
#define CC 3
#define NCC (NN*CC)        // 192 rows
#define LL 4096
#define KK 128             // shapelets
#define SS 64              // shapelet length
#define WW (LL - SS + 1)   // 4033 valid windows
#define GROUPS 6           // window groups per nc row
#define WPC 704            // windows per CTA (11 tiles of 64; 6*704=4224 >= 4033)
#define TILES 11
#define GRID (NCC*GROUPS)  // 1152 CTAs
#define TMAIN 256

#define STRIP 784          // f32 strip elements (704 + 64 + pad)
#define PSTR  388          // parity-pair words

// ---------------------------------------------------------------- scratch
__device__ uint32_t g_shp[CC*KK*32]; // shapelet fp16 pairs, row-major (32 u32 per k-row)
__device__ float    g_s2[CC*KK];     // ||s||^2
__device__ int      g_minb[NN*KK];   // running min d^2 (int bits)
__device__ int      g_ctr;           // completion counter (zero-init, self-reset)

__device__ __forceinline__ uint32_t packh(float a, float b) {
    __half2 h = __floats2half2_rn(a, b);   // low = a, high = b
    return *(uint32_t*)&h;
}

// ---------------------------------------------------------------- prep (tiny)
__global__ __launch_bounds__(256) void prep_kernel(const float* __restrict__ sh) {
    int t = blockIdx.x * blockDim.x + threadIdx.x;
    int nt = gridDim.x * blockDim.x;
    for (int i = t; i < CC * KK * 32; i += nt) {
        int base = (i >> 5) * SS + (i & 31) * 2;
        g_shp[i] = packh(sh[base], sh[base + 1]);
    }
    for (int i = t; i < CC * KK; i += nt) {
        const float* p = sh + i * SS;
        float s = 0.f;
#pragma unroll
        for (int j = 0; j < SS; j++) s = fmaf(p[j], p[j], s);
        g_s2[i] = s;
    }
    for (int i = t; i < NN * KK; i += nt) g_minb[i] = 0x7F800000;  // +inf
}

// ---------------------------------------------------------------- mma wrappers
__device__ __forceinline__ void mma16816(float& c0, float& c1, float& c2, float& c3,
                                         uint32_t a0, uint32_t a1, uint32_t a2, uint32_t a3,
                                         uint32_t b0, uint32_t b1) {
    asm("mma.sync.aligned.m16n8k16.row.col.f32.f16.f16.f32 "
        "{%0,%1,%2,%3}, {%4,%5,%6,%7}, {%8,%9}, {%0,%1,%2,%3};"
        : "+f"(c0), "+f"(c1), "+f"(c2), "+f"(c3)
        : "r"(a0), "r"(a1), "r"(a2), "r"(a3), "r"(b0), "r"(b1));
}
// out-of-place with zero C: no accumulator init needed
__device__ __forceinline__ void mma16816_z(float& c0, float& c1, float& c2, float& c3,
                                           uint32_t a0, uint32_t a1, uint32_t a2, uint32_t a3,
                                           uint32_t b0, uint32_t b1) {
    float z = 0.f;
    asm("mma.sync.aligned.m16n8k16.row.col.f32.f16.f16.f32 "
        "{%0,%1,%2,%3}, {%4,%5,%6,%7}, {%8,%9}, {%10,%10,%10,%10};"
        : "=f"(c0), "=f"(c1), "=f"(c2), "=f"(c3)
        : "r"(a0), "r"(a1), "r"(a2), "r"(a3), "r"(b0), "r"(b1), "f"(z));
}

// ---------------------------------------------------------------- main
// CTA = (nc row, group of 704 windows = 11 tiles of 64).
// Prologue: stage A tile to smem (coalesced), f32 strip, fp16 parity packs,
// sliding-update window norms. 8 warps: wm=warp%4 (32 k-rows), wn=warp/4
// (32 windows of each 64-tile). B frags straight from parity strip (Hankel).
__global__ __launch_bounds__(TMAIN) void main_kernel(const float* __restrict__ x,
                                                     float* __restrict__ out) {
    __shared__ float xs[STRIP];
    __shared__ uint32_t SE[PSTR], SO[PSTR];
    __shared__ float x2s[WPC];
    __shared__ uint32_t As[KK * 33];        // stride-33: conflict-free frag reads

    int b = blockIdx.x;
    int nc = b / GROUPS, grp = b % GROUPS;
    int c = nc % CC, n = nc / CC;
    int tid = threadIdx.x, lane = tid & 31, warp = tid >> 5;
    int wm = warp & 3, wn = warp >> 2;
    int q = lane & 3, g = lane >> 2;

    int ebase = grp * WPC;
    const float* xr = x + nc * LL;

    // 1) stage shapelet tile (channel c) into smem, coalesced
    {
        const uint32_t* src = g_shp + c * (KK * 32);
        for (int i = tid; i < KK * 32; i += TMAIN)
            As[(i >> 5) * 33 + (i & 31)] = src[i];
    }
    // 2) f32 strip (zero-padded past row end)
    for (int i = tid; i < STRIP; i += TMAIN) {
        int gidx = ebase + i;
        xs[i] = (gidx < LL) ? xr[gidx] : 0.f;
    }
    __syncthreads();

    // 3) fp16 parity packs
    for (int i = tid; i < PSTR; i += TMAIN) {
        float e0 = xs[2 * i], e1 = xs[2 * i + 1], e2 = xs[2 * i + 2];
        SE[i] = packh(e0, e1);
        SO[i] = packh(e1, e2);
    }
    // 4) window norms: 3 windows/thread via sliding update (near-exact)
    {
        int w0 = tid * 3;
        if (w0 < WPC) {
            float s = 0.f;
#pragma unroll
            for (int i = 0; i < SS; i++) { float v = xs[w0 + i]; s = fmaf(v, v, s); }
            x2s[w0] = (ebase + w0 < WW) ? s : CUDART_INF_F;
#pragma unroll
            for (int r = 1; r < 3; r++) {
                int w = w0 + r;
                float vin = xs[w + SS - 1], vout = xs[w - 1];
                s = fmaf(vin, vin, fmaf(-vout, vout, s));
                if (w < WPC) x2s[w] = (ebase + w < WW) ? s : CUDART_INF_F;
            }
        }
    }
    __syncthreads();

    // 5) A fragments: regs from smem (conflict-free), rows wm*32..wm*32+31
    uint32_t A[2][4][4];
    float s2v[2][2];
#pragma unroll
    for (int mt = 0; mt < 2; mt++) {
        int r0 = wm * 32 + mt * 16 + g;
        int r1 = r0 + 8;
        const uint32_t* ap0 = As + r0 * 33;
        const uint32_t* ap1 = As + r1 * 33;
#pragma unroll
        for (int ks = 0; ks < 4; ks++) {
            A[mt][ks][0] = ap0[ks * 8 + q];
            A[mt][ks][1] = ap1[ks * 8 + q];
            A[mt][ks][2] = ap0[ks * 8 + q + 4];
            A[mt][ks][3] = ap1[ks * 8 + q + 4];
        }
        s2v[mt][0] = g_s2[c * KK + r0];
        s2v[mt][1] = g_s2[c * KK + r1];
    }

    // per-lane strip pointer (parity of element index = g&1)
    const uint32_t* sp = ((g & 1) ? SO : SE) + (g >> 1) + q + wn * 16;

    float mn[2][2] = {{CUDART_INF_F, CUDART_INF_F}, {CUDART_INF_F, CUDART_INF_F}};

#pragma unroll 1
    for (int t = 0; t < TILES; t++) {
        float acc[2][4][4];
#pragma unroll
        for (int nt = 0; nt < 4; nt++) {
            {   // ks = 0: zero-C out-of-place
                uint32_t b0 = sp[t * 32 + nt * 4];
                uint32_t b1 = sp[t * 32 + nt * 4 + 4];
                mma16816_z(acc[0][nt][0], acc[0][nt][1], acc[0][nt][2], acc[0][nt][3],
                           A[0][0][0], A[0][0][1], A[0][0][2], A[0][0][3], b0, b1);
                mma16816_z(acc[1][nt][0], acc[1][nt][1], acc[1][nt][2], acc[1][nt][3],
                           A[1][0][0], A[1][0][1], A[1][0][2], A[1][0][3], b0, b1);
            }
#pragma unroll
            for (int ks = 1; ks < 4; ks++) {
                uint32_t b0 = sp[t * 32 + nt * 4 + ks * 8];
                uint32_t b1 = sp[t * 32 + nt * 4 + ks * 8 + 4];
                mma16816(acc[0][nt][0], acc[0][nt][1], acc[0][nt][2], acc[0][nt][3],
                         A[0][ks][0], A[0][ks][1], A[0][ks][2], A[0][ks][3], b0, b1);
                mma16816(acc[1][nt][0], acc[1][nt][1], acc[1][nt][2], acc[1][nt][3],
                         A[1][ks][0], A[1][ks][1], A[1][ks][2], A[1][ks][3], b0, b1);
            }
        }

        // epilogue: track min(x2[w] - 2*dot); +s2 folded in at the end
#pragma unroll
        for (int nt = 0; nt < 4; nt++) {
            int col = t * 64 + wn * 32 + nt * 8 + q * 2;
            float2 xv = *(const float2*)&x2s[col];
#pragma unroll
            for (int mt = 0; mt < 2; mt++) {
                mn[mt][0] = fminf(mn[mt][0], fmaf(-2.f, acc[mt][nt][0], xv.x));
                mn[mt][0] = fminf(mn[mt][0], fmaf(-2.f, acc[mt][nt][1], xv.y));
                mn[mt][1] = fminf(mn[mt][1], fmaf(-2.f, acc[mt][nt][2], xv.x));
                mn[mt][1] = fminf(mn[mt][1], fmaf(-2.f, acc[mt][nt][3], xv.y));
            }
        }
    }

    // reduce over the 4 lanes sharing the same rows (same g, q = 0..3)
#pragma unroll
    for (int mt = 0; mt < 2; mt++)
#pragma unroll
        for (int h = 0; h < 2; h++) {
            float v = mn[mt][h];
            v = fminf(v, __shfl_xor_sync(0xFFFFFFFFu, v, 1));
            v = fminf(v, __shfl_xor_sync(0xFFFFFFFFu, v, 2));
            if (q == 0) {
                int row = wm * 32 + mt * 16 + h * 8 + g;
                atomicMin(&g_minb[n * KK + row], __float_as_int(v + s2v[mt][h]));
            }
        }

    // last CTA finalizes: sqrt(min d^2) -> out
    __shared__ int lastFlag;
    __threadfence();
    __syncthreads();
    if (tid == 0) lastFlag = (atomicAdd(&g_ctr, 1) == GRID - 1);
    __syncthreads();
    if (lastFlag) {
        __threadfence();
        for (int i = tid; i < NN * KK; i += TMAIN) {
            float d2 = __int_as_float(g_minb[i]);
            out[i] = sqrtf(fmaxf(d2, 0.f));
        }
        __threadfence();
        if (tid == 0) g_ctr = 0;
    }
}

// ---------------------------------------------------------------- launch
extern "C" void kernel_launch(void* const* d_in, const int* in_sizes, int n_in,
                              void* d_out, int out_size) {
    const float* x  = (const float*)d_in[0];
    const float* sh = (const float*)d_in[1];
    if (n_in >= 2 && in_sizes[0] == CC * KK * SS && in_sizes[1] == NN * CC * LL) {
        x  = (const float*)d_in[1];
        sh = (const float*)d_in[0];
    }
    prep_kernel<<<8, 256>>>(sh);
    main_kernel<<<GRID, TMAIN>>>(x, (float*)d_out);
}

// round 6
// speedup vs baseline: 6.3349x; 1.0061x over previous
#include <cuda_runtime.h>
#include <cuda_fp16.h>
#include <math_constants.h>
#include <cstdint>

// ---------------------------------------------------------------- constants
#define NN 64
#define CC 3
#define NCC (NN*CC)        // 192 rows
#define LL 4096
#define KK 128             // shapelets
#define SS 64              // shapelet length
#define WW (LL - SS + 1)   // 4033 valid windows
#define GROUPS 6           // window groups per nc row
#define WPC 704            // windows per CTA (11 tiles of 64; 6*704=4224 >= 4033)
#define TILES 11
#define GRID (NCC*GROUPS)  // 1152 CTAs
#define TMAIN 256

#define STRIP 784          // f32 strip elements (704 + 64 + pad)
#define PSTR  388          // parity-pair words

// ---------------------------------------------------------------- scratch
__device__ uint32_t g_shp[CC*KK*32]; // shapelet fp16 pairs, row-major (32 u32 per k-row)
__device__ float    g_s2[CC*KK];     // ||s||^2
__device__ int      g_minb[NN*KK];   // running min d^2 (int bits)
__device__ int      g_ctr;           // completion counter (zero-init, self-reset)

__device__ __forceinline__ uint32_t packh(float a, float b) {
    __half2 h = __floats2half2_rn(a, b);   // low = a, high = b
    return *(uint32_t*)&h;
}

// ---------------------------------------------------------------- prep (tiny)
__global__ __launch_bounds__(256) void prep_kernel(const float* __restrict__ sh) {
    int t = blockIdx.x * blockDim.x + threadIdx.x;
    int nt = gridDim.x * blockDim.x;
    for (int i = t; i < CC * KK * 32; i += nt) {
        int base = (i >> 5) * SS + (i & 31) * 2;
        g_shp[i] = packh(sh[base], sh[base + 1]);
    }
    for (int i = t; i < CC * KK; i += nt) {
        const float* p = sh + i * SS;
        float s = 0.f;
#pragma unroll
        for (int j = 0; j < SS; j++) s = fmaf(p[j], p[j], s);
        g_s2[i] = s;
    }
    for (int i = t; i < NN * KK; i += nt) g_minb[i] = 0x7F800000;  // +inf
}

// ---------------------------------------------------------------- mma wrappers
__device__ __forceinline__ void mma16816(float& c0, float& c1, float& c2, float& c3,
                                         uint32_t a0, uint32_t a1, uint32_t a2, uint32_t a3,
                                         uint32_t b0, uint32_t b1) {
    asm("mma.sync.aligned.m16n8k16.row.col.f32.f16.f16.f32 "
        "{%0,%1,%2,%3}, {%4,%5,%6,%7}, {%8,%9}, {%0,%1,%2,%3};"
        : "+f"(c0), "+f"(c1), "+f"(c2), "+f"(c3)
        : "r"(a0), "r"(a1), "r"(a2), "r"(a3), "r"(b0), "r"(b1));
}
// out-of-place with zero C: no accumulator init needed
__device__ __forceinline__ void mma16816_z(float& c0, float& c1, float& c2, float& c3,
                                           uint32_t a0, uint32_t a1, uint32_t a2, uint32_t a3,
                                           uint32_t b0, uint32_t b1) {
    float z = 0.f;
    asm("mma.sync.aligned.m16n8k16.row.col.f32.f16.f16.f32 "
        "{%0,%1,%2,%3}, {%4,%5,%6,%7}, {%8,%9}, {%10,%10,%10,%10};"
        : "=f"(c0), "=f"(c1), "=f"(c2), "=f"(c3)
        : "r"(a0), "r"(a1), "r"(a2), "r"(a3), "r"(b0), "r"(b1), "f"(z));
}

// ---------------------------------------------------------------- main
// CTA = (nc row, group of 704 windows = 11 tiles of 64).
// Hankel B reuse: only 11 distinct B words per lane per tile -> register ring.
__global__ __launch_bounds__(TMAIN, 3) void main_kernel(const float* __restrict__ x,
                                                        float* __restrict__ out) {
    __shared__ float xs[STRIP];
    __shared__ uint32_t SE[PSTR], SO[PSTR];
    __shared__ float x2s[WPC];
    __shared__ uint32_t As[KK * 33];        // stride-33: conflict-free frag reads

    int b = blockIdx.x;
    int nc = b / GROUPS, grp = b % GROUPS;
    int c = nc % CC, n = nc / CC;
    int tid = threadIdx.x, lane = tid & 31, warp = tid >> 5;
    int wm = warp & 3, wn = warp >> 2;
    int q = lane & 3, g = lane >> 2;

    int ebase = grp * WPC;
    const float* xr = x + nc * LL;

    // 1) stage shapelet tile (channel c) into smem, coalesced
    {
        const uint32_t* src = g_shp + c * (KK * 32);
        for (int i = tid; i < KK * 32; i += TMAIN)
            As[(i >> 5) * 33 + (i & 31)] = src[i];
    }
    // 2) f32 strip (zero-padded past row end)
    for (int i = tid; i < STRIP; i += TMAIN) {
        int gidx = ebase + i;
        xs[i] = (gidx < LL) ? xr[gidx] : 0.f;
    }
    __syncthreads();

    // 3) fp16 parity packs
    for (int i = tid; i < PSTR; i += TMAIN) {
        float e0 = xs[2 * i], e1 = xs[2 * i + 1], e2 = xs[2 * i + 2];
        SE[i] = packh(e0, e1);
        SO[i] = packh(e1, e2);
    }
    // 4) window norms: 3 windows/thread via sliding update (near-exact)
    {
        int w0 = tid * 3;
        if (w0 < WPC) {
            float s = 0.f;
#pragma unroll
            for (int i = 0; i < SS; i++) { float v = xs[w0 + i]; s = fmaf(v, v, s); }
            x2s[w0] = (ebase + w0 < WW) ? s : CUDART_INF_F;
#pragma unroll
            for (int r = 1; r < 3; r++) {
                int w = w0 + r;
                float vin = xs[w + SS - 1], vout = xs[w - 1];
                s = fmaf(vin, vin, fmaf(-vout, vout, s));
                if (w < WPC) x2s[w] = (ebase + w < WW) ? s : CUDART_INF_F;
            }
        }
    }
    __syncthreads();

    // 5) A fragments: regs from smem (conflict-free), rows wm*32..wm*32+31
    uint32_t A[2][4][4];
    float s2v[2][2];
#pragma unroll
    for (int mt = 0; mt < 2; mt++) {
        int r0 = wm * 32 + mt * 16 + g;
        int r1 = r0 + 8;
        const uint32_t* ap0 = As + r0 * 33;
        const uint32_t* ap1 = As + r1 * 33;
#pragma unroll
        for (int ks = 0; ks < 4; ks++) {
            A[mt][ks][0] = ap0[ks * 8 + q];
            A[mt][ks][1] = ap1[ks * 8 + q];
            A[mt][ks][2] = ap0[ks * 8 + q + 4];
            A[mt][ks][3] = ap1[ks * 8 + q + 4];
        }
        s2v[mt][0] = g_s2[c * KK + r0];
        s2v[mt][1] = g_s2[c * KK + r1];
    }

    // per-lane strip pointer (parity of element index = g&1)
    const uint32_t* sp = ((g & 1) ? SO : SE) + (g >> 1) + q + wn * 16;

    float mn[2][2] = {{CUDART_INF_F, CUDART_INF_F}, {CUDART_INF_F, CUDART_INF_F}};

#pragma unroll 1
    for (int t = 0; t < TILES; t++) {
        // 11 distinct B words cover all (nt, ks) fragments of this tile
        uint32_t Bw[11];
#pragma unroll
        for (int j = 0; j < 11; j++) Bw[j] = sp[t * 32 + j * 4];

#pragma unroll
        for (int nt = 0; nt < 4; nt++) {
            float a0c[4], a1c[4];
            mma16816_z(a0c[0], a0c[1], a0c[2], a0c[3],
                       A[0][0][0], A[0][0][1], A[0][0][2], A[0][0][3],
                       Bw[nt], Bw[nt + 1]);
            mma16816_z(a1c[0], a1c[1], a1c[2], a1c[3],
                       A[1][0][0], A[1][0][1], A[1][0][2], A[1][0][3],
                       Bw[nt], Bw[nt + 1]);
#pragma unroll
            for (int ks = 1; ks < 4; ks++) {
                mma16816(a0c[0], a0c[1], a0c[2], a0c[3],
                         A[0][ks][0], A[0][ks][1], A[0][ks][2], A[0][ks][3],
                         Bw[nt + 2 * ks], Bw[nt + 2 * ks + 1]);
                mma16816(a1c[0], a1c[1], a1c[2], a1c[3],
                         A[1][ks][0], A[1][ks][1], A[1][ks][2], A[1][ks][3],
                         Bw[nt + 2 * ks], Bw[nt + 2 * ks + 1]);
            }
            // epilogue: min(x2[w] - 2*dot); +s2 folded at the end
            int col = t * 64 + wn * 32 + nt * 8 + q * 2;
            float2 xv = *(const float2*)&x2s[col];
            mn[0][0] = fminf(mn[0][0], fmaf(-2.f, a0c[0], xv.x));
            mn[0][0] = fminf(mn[0][0], fmaf(-2.f, a0c[1], xv.y));
            mn[0][1] = fminf(mn[0][1], fmaf(-2.f, a0c[2], xv.x));
            mn[0][1] = fminf(mn[0][1], fmaf(-2.f, a0c[3], xv.y));
            mn[1][0] = fminf(mn[1][0], fmaf(-2.f, a1c[0], xv.x));
            mn[1][0] = fminf(mn[1][0], fmaf(-2.f, a1c[1], xv.y));
            mn[1][1] = fminf(mn[1][1], fmaf(-2.f, a1c[2], xv.x));
            mn[1][1] = fminf(mn[1][1], fmaf(-2.f, a1c[3], xv.y));
        }
    }

    // reduce over the 4 lanes sharing the same rows (same g, q = 0..3)
#pragma unroll
    for (int mt = 0; mt < 2; mt++)
#pragma unroll
        for (int h = 0; h < 2; h++) {
            float v = mn[mt][h];
            v = fminf(v, __shfl_xor_sync(0xFFFFFFFFu, v, 1));
            v = fminf(v, __shfl_xor_sync(0xFFFFFFFFu, v, 2));
            if (q == 0) {
                int row = wm * 32 + mt * 16 + h * 8 + g;
                atomicMin(&g_minb[n * KK + row], __float_as_int(v + s2v[mt][h]));
            }
        }

    // last CTA finalizes: sqrt(min d^2) -> out
    __shared__ int lastFlag;
    __threadfence();
    __syncthreads();
    if (tid == 0) lastFlag = (atomicAdd(&g_ctr, 1) == GRID - 1);
    __syncthreads();
    if (lastFlag) {
        __threadfence();
        for (int i = tid; i < NN * KK; i += TMAIN) {
            float d2 = __int_as_float(g_minb[i]);
            out[i] = sqrtf(fmaxf(d2, 0.f));
        }
        __threadfence();
        if (tid == 0) g_ctr = 0;
    }
}

// ---------------------------------------------------------------- launch
extern "C" void kernel_launch(void* const* d_in, const int* in_sizes, int n_in,
                              void* d_out, int out_size) {
    const float* x  = (const float*)d_in[0];
    const float* sh = (const float*)d_in[1];
    if (n_in >= 2 && in_sizes[0] == CC * KK * SS && in_sizes[1] == NN * CC * LL) {
        x  = (const float*)d_in[1];
        sh = (const float*)d_in[0];
    }
    prep_kernel<<<8, 256>>>(sh);
    main_kernel<<<GRID, TMAIN>>>(x, (float*)d_out);
}